// round 2
// baseline (speedup 1.0000x reference)
#include <cuda_runtime.h>
#include <math.h>

// Shapes (fixed for this problem)
#define QL 1024
#define CL 2048
#define BATCH 16
#define DIM 1024

#define BM 128
#define BN 128
#define BK 8
#define PAD 132   // padded smem row (in floats): conflict-free + 16B-aligned rows

// Scratch: qb and ctx, [b, q, dim] each = 64 MB
__device__ float g_qb [(size_t)BATCH * QL * DIM];
__device__ float g_ctx[(size_t)BATCH * QL * DIM];

// ---------------------------------------------------------------------------
// C = A * B^T  (A: M x K, K-contiguous with row stride lda;
//               B: N x K, K-contiguous with row stride ldb)
// Optional: CONCAT (A is [A0 | A1] along K, split at Ksplit), TANH epilogue.
// Tiles: 128x128x8, 256 threads, 8x8 per-thread register tile.
// ---------------------------------------------------------------------------
template<bool TANH, bool CONCAT>
__global__ __launch_bounds__(256, 2)
void gemm_tt_kernel(const float* __restrict__ A0, const float* __restrict__ A1,
                    long lda, long sAb,
                    const float* __restrict__ B, long ldb, long sBb,
                    float* __restrict__ C, long ldc, long sCb,
                    int K, int Ksplit)
{
    __shared__ float As[BK][PAD];
    __shared__ float Bs[BK][PAD];

    const int bi = blockIdx.z;
    const float* Ab0 = A0 + (long)bi * sAb;
    const float* Ab1 = CONCAT ? (A1 + (long)bi * sAb) : Ab0;
    const float* Bb  = B  + (long)bi * sBb;
    float*       Cb  = C  + (long)bi * sCb;

    const int m0 = blockIdx.y * BM;
    const int n0 = blockIdx.x * BN;
    const int tid  = threadIdx.x;
    const int lrow = tid >> 1;          // 0..127: tile row for global loads
    const int lk   = (tid & 1) * 4;     // 0 or 4: k offset for global loads
    const int tx   = tid & 15;
    const int ty   = tid >> 4;

    float acc[8][8];
    #pragma unroll
    for (int i = 0; i < 8; i++)
        #pragma unroll
        for (int j = 0; j < 8; j++) acc[i][j] = 0.f;

    for (int k0 = 0; k0 < K; k0 += BK) {
        const float* Aptr;
        int ka;
        if (CONCAT && k0 >= Ksplit) { Aptr = Ab1; ka = k0 - Ksplit; }
        else                        { Aptr = Ab0; ka = k0; }

        float4 av = *(const float4*)(Aptr + (long)(m0 + lrow) * lda + ka + lk);
        float4 bv = *(const float4*)(Bb   + (long)(n0 + lrow) * ldb + k0 + lk);

        __syncthreads();
        As[lk + 0][lrow] = av.x; As[lk + 1][lrow] = av.y;
        As[lk + 2][lrow] = av.z; As[lk + 3][lrow] = av.w;
        Bs[lk + 0][lrow] = bv.x; Bs[lk + 1][lrow] = bv.y;
        Bs[lk + 2][lrow] = bv.z; Bs[lk + 3][lrow] = bv.w;
        __syncthreads();

        #pragma unroll
        for (int kk = 0; kk < BK; kk++) {
            float a[8], b8[8];
            *(float4*)(a)     = *(const float4*)&As[kk][ty * 8];
            *(float4*)(a + 4) = *(const float4*)&As[kk][ty * 8 + 4];
            *(float4*)(b8)     = *(const float4*)&Bs[kk][tx * 8];
            *(float4*)(b8 + 4) = *(const float4*)&Bs[kk][tx * 8 + 4];
            #pragma unroll
            for (int i = 0; i < 8; i++)
                #pragma unroll
                for (int j = 0; j < 8; j++)
                    acc[i][j] += a[i] * b8[j];
        }
    }

    #pragma unroll
    for (int i = 0; i < 8; i++) {
        long rbase = (long)(m0 + ty * 8 + i) * ldc + n0 + tx * 8;
        #pragma unroll
        for (int j = 0; j < 8; j += 4) {
            float4 o;
            o.x = TANH ? tanhf(acc[i][j + 0]) : acc[i][j + 0];
            o.y = TANH ? tanhf(acc[i][j + 1]) : acc[i][j + 1];
            o.z = TANH ? tanhf(acc[i][j + 2]) : acc[i][j + 2];
            o.w = TANH ? tanhf(acc[i][j + 3]) : acc[i][j + 3];
            *(float4*)(Cb + rbase + j) = o;
        }
    }
}

// ---------------------------------------------------------------------------
// C = A * B  (A: M x K, K-contiguous, row stride lda;
//             B: K x N, N-contiguous, row stride ldb)
// ---------------------------------------------------------------------------
__global__ __launch_bounds__(256, 2)
void gemm_tn_kernel(const float* __restrict__ A, long lda, long sAb,
                    const float* __restrict__ B, long ldb, long sBb,
                    float* __restrict__ C, long ldc, long sCb, int K)
{
    __shared__ float As[BK][PAD];
    __shared__ float Bs[BK][PAD];

    const int bi = blockIdx.z;
    const float* Ab = A + (long)bi * sAb;
    const float* Bb = B + (long)bi * sBb;
    float*       Cb = C + (long)bi * sCb;

    const int m0 = blockIdx.y * BM;
    const int n0 = blockIdx.x * BN;
    const int tid  = threadIdx.x;
    const int lrow = tid >> 1;
    const int lk   = (tid & 1) * 4;
    const int brow = tid >> 5;          // 0..7: B tile k-row
    const int bcol = (tid & 31) * 4;    // 0..124
    const int tx   = tid & 15;
    const int ty   = tid >> 4;

    float acc[8][8];
    #pragma unroll
    for (int i = 0; i < 8; i++)
        #pragma unroll
        for (int j = 0; j < 8; j++) acc[i][j] = 0.f;

    for (int k0 = 0; k0 < K; k0 += BK) {
        float4 av = *(const float4*)(Ab + (long)(m0 + lrow) * lda + k0 + lk);
        float4 bv = *(const float4*)(Bb + (long)(k0 + brow) * ldb + n0 + bcol);

        __syncthreads();
        As[lk + 0][lrow] = av.x; As[lk + 1][lrow] = av.y;
        As[lk + 2][lrow] = av.z; As[lk + 3][lrow] = av.w;
        *(float4*)&Bs[brow][bcol] = bv;
        __syncthreads();

        #pragma unroll
        for (int kk = 0; kk < BK; kk++) {
            float a[8], b8[8];
            *(float4*)(a)     = *(const float4*)&As[kk][ty * 8];
            *(float4*)(a + 4) = *(const float4*)&As[kk][ty * 8 + 4];
            *(float4*)(b8)     = *(const float4*)&Bs[kk][tx * 8];
            *(float4*)(b8 + 4) = *(const float4*)&Bs[kk][tx * 8 + 4];
            #pragma unroll
            for (int i = 0; i < 8; i++)
                #pragma unroll
                for (int j = 0; j < 8; j++)
                    acc[i][j] += a[i] * b8[j];
        }
    }

    #pragma unroll
    for (int i = 0; i < 8; i++) {
        long rbase = (long)(m0 + ty * 8 + i) * ldc + n0 + tx * 8;
        #pragma unroll
        for (int j = 0; j < 8; j += 4) {
            float4 o;
            o.x = acc[i][j + 0]; o.y = acc[i][j + 1];
            o.z = acc[i][j + 2]; o.w = acc[i][j + 3];
            *(float4*)(Cb + rbase + j) = o;
        }
    }
}

// ---------------------------------------------------------------------------
// In-place softmax over rows of 2048 (one block per row, 256 threads x 8 elems)
// ---------------------------------------------------------------------------
__global__ __launch_bounds__(256)
void softmax2048_kernel(float* __restrict__ S)
{
    float* row = S + (long)blockIdx.x * 2048;
    const int t = threadIdx.x;
    __shared__ float sred[8];

    float v[8];
    float mx = -3.402823466e38f;
    #pragma unroll
    for (int j = 0; j < 8; j++) {
        v[j] = row[t + j * 256];
        mx = fmaxf(mx, v[j]);
    }
    #pragma unroll
    for (int o = 16; o > 0; o >>= 1)
        mx = fmaxf(mx, __shfl_xor_sync(0xffffffffu, mx, o));
    if ((t & 31) == 0) sred[t >> 5] = mx;
    __syncthreads();
    mx = sred[0];
    #pragma unroll
    for (int w = 1; w < 8; w++) mx = fmaxf(mx, sred[w]);

    float s = 0.f;
    #pragma unroll
    for (int j = 0; j < 8; j++) {
        v[j] = expf(v[j] - mx);
        s += v[j];
    }
    #pragma unroll
    for (int o = 16; o > 0; o >>= 1)
        s += __shfl_xor_sync(0xffffffffu, s, o);
    __syncthreads();
    if ((t & 31) == 0) sred[t >> 5] = s;
    __syncthreads();
    s = 0.f;
    #pragma unroll
    for (int w = 0; w < 8; w++) s += sred[w];

    float inv = 1.f / s;
    #pragma unroll
    for (int j = 0; j < 8; j++)
        row[t + j * 256] = v[j] * inv;
}

// ---------------------------------------------------------------------------
extern "C" void kernel_launch(void* const* d_in, const int* in_sizes, int n_in,
                              void* d_out, int out_size)
{
    (void)in_sizes; (void)n_in; (void)out_size;
    const float* q     = (const float*)d_in[0];   // [QL, B, DIM]
    const float* c     = (const float*)d_in[1];   // [CL, B, DIM]
    const float* W_in  = (const float*)d_in[2];   // [DIM, DIM]
    const float* W_out = (const float*)d_in[3];   // [DIM, 2*DIM]

    float* out   = (float*)d_out;                         // [QL, B, DIM]
    float* score = out + (size_t)QL * BATCH * DIM;        // [B, QL, CL]

    float* qb  = nullptr;
    float* ctx = nullptr;
    cudaGetSymbolAddress((void**)&qb,  g_qb);
    cudaGetSymbolAddress((void**)&ctx, g_ctx);

    const long sQB  = (long)QL * DIM;      // 1M  per batch
    const long sSC  = (long)QL * CL;       // 2M  per batch

    // Stage 1: qb[b,q,e] = sum_d q[q,b,d] * W_in[e,d]
    {
        dim3 grid(DIM / BN, QL / BM, BATCH);
        gemm_tt_kernel<false, false><<<grid, 256>>>(
            q, nullptr, /*lda*/ (long)BATCH * DIM, /*sAb*/ DIM,
            W_in, /*ldb*/ DIM, /*sBb*/ 0,
            qb, /*ldc*/ DIM, /*sCb*/ sQB,
            DIM, 0);
    }

    // Stage 2: raw score[b,q,k] = sum_d qb[b,q,d] * c[k,b,d]  -> score region
    {
        dim3 grid(CL / BN, QL / BM, BATCH);
        gemm_tt_kernel<false, false><<<grid, 256>>>(
            qb, nullptr, /*lda*/ DIM, /*sAb*/ sQB,
            c, /*ldb*/ (long)BATCH * DIM, /*sBb*/ DIM,
            score, /*ldc*/ CL, /*sCb*/ sSC,
            DIM, 0);
    }

    // Stage 3: softmax in place over last dim (CL=2048)
    softmax2048_kernel<<<BATCH * QL, 256>>>(score);

    // Stage 4: ctx[b,q,d] = sum_k score[b,q,k] * c[k,b,d]
    {
        dim3 grid(DIM / BN, QL / BM, BATCH);
        gemm_tn_kernel<<<grid, 256>>>(
            score, /*lda*/ CL, /*sAb*/ sSC,
            c, /*ldb*/ (long)BATCH * DIM, /*sBb*/ DIM,
            ctx, /*ldc*/ DIM, /*sCb*/ sQB,
            CL);
    }

    // Stage 5: out[q,b,d] = tanh( sum_f [ctx|qb][b,q,f] * W_out[d,f] )
    {
        dim3 grid(DIM / BN, QL / BM, BATCH);
        gemm_tt_kernel<true, true><<<grid, 256>>>(
            ctx, qb, /*lda*/ DIM, /*sAb*/ sQB,
            W_out, /*ldb*/ 2 * DIM, /*sBb*/ 0,
            out + /*batch base via sCb*/ 0, /*ldc*/ (long)BATCH * DIM, /*sCb*/ DIM,
            2 * DIM, DIM);
    }
}